// round 6
// baseline (speedup 1.0000x reference)
#include <cuda_runtime.h>

#define BB 32
#define TT 2048
#define DD 1024
#define CHUNK 64
#define EGRID 888        // 148 SMs * 6 resident blocks (regs=40, 256 thr)

// Device scratch (no allocation allowed in kernel_launch)
__device__ float g_energies[BB * TT];
__device__ int   g_prefix[BB + 1];   // prefix sums of lens; [BB] = total rows

__device__ __forceinline__ float fast_tanh(float x) {
    float y;
    asm("tanh.approx.f32 %0, %1;" : "=f"(y) : "f"(x));
    return y;
}

// ---------------------------------------------------------------------------
// Kernel 0: prefix sums of lens (1 warp does it all; B=32).
// ---------------------------------------------------------------------------
__global__ void prefix_kernel(const int* __restrict__ lens)
{
    const int i = threadIdx.x;            // 0..31
    int v = __ldg(lens + i);
    int s = v;
    #pragma unroll
    for (int o = 1; o < 32; o <<= 1) {    // inclusive scan
        int up = __shfl_up_sync(0xffffffffu, s, o);
        if (i >= o) s += up;
    }
    g_prefix[i + 1] = s;                  // exclusive at [i] = inclusive[i-1]
    if (i == 0) g_prefix[0] = 0;
}

// ---------------------------------------------------------------------------
// Kernel 1: energies[b,t] = sum_d v[d] * tanh(keys[b,t,d] + query[b,d] + wf[b,t,d])
// Persistent warp-per-row over ACTIVE rows only: grid-stride on the active row
// index, (b,t) via binary search in the smem prefix table. No empty blocks,
// no barriers in the row loop -> next-row loads overlap current-row math tail.
// ---------------------------------------------------------------------------
__global__ void __launch_bounds__(256) energy_kernel(
    const float* __restrict__ keys,
    const float* __restrict__ query,
    const float* __restrict__ wf,
    const float* __restrict__ v)
{
    __shared__ int sp[BB + 1];
    if (threadIdx.x <= BB) sp[threadIdx.x] = g_prefix[threadIdx.x];
    __syncthreads();
    const int total = sp[BB];

    const int warp = threadIdx.x >> 5;
    const int lane = threadIdx.x & 31;
    const float4* v4 = reinterpret_cast<const float4*>(v);

    for (int r = blockIdx.x * 8 + warp; r < total; r += EGRID * 8) {
        // binary search: largest b with sp[b] <= r
        int lo = 0, hi = BB;
        #pragma unroll
        for (int it = 0; it < 5; ++it) {
            int mid = (lo + hi) >> 1;
            if (sp[mid] <= r) lo = mid; else hi = mid;
        }
        const int b = lo;
        const int t = r - sp[lo];

        const size_t row = ((size_t)b * TT + t) * DD;
        const float4* k4 = reinterpret_cast<const float4*>(keys + row);
        const float4* f4 = reinterpret_cast<const float4*>(wf + row);
        const float4* q4 = reinterpret_cast<const float4*>(query + (size_t)b * DD);

        float s = 0.0f;
        #pragma unroll
        for (int j = 0; j < DD / 4 / 32; ++j) {   // 8 iterations
            const int idx = lane + 32 * j;
            float4 kk = k4[idx];
            float4 ff = f4[idx];
            float4 qq = __ldg(q4 + idx);
            float4 vv = __ldg(v4 + idx);
            s += vv.x * fast_tanh(kk.x + qq.x + ff.x)
               + vv.y * fast_tanh(kk.y + qq.y + ff.y)
               + vv.z * fast_tanh(kk.z + qq.z + ff.z)
               + vv.w * fast_tanh(kk.w + qq.w + ff.w);
        }

        #pragma unroll
        for (int o = 16; o; o >>= 1) s += __shfl_xor_sync(0xffffffffu, s, o);
        if (lane == 0) g_energies[b * TT + t] = s;
    }
}

// ---------------------------------------------------------------------------
// Kernel 2: per-batch masked softmax -> weights region; zero context region.
// ---------------------------------------------------------------------------
__global__ void __launch_bounds__(256) softmax_kernel(
    const int* __restrict__ lens,
    float* __restrict__ out)
{
    const int b = blockIdx.x;
    const int len = __ldg(lens + b);
    const float* e = g_energies + b * TT;
    float* wout = out + (size_t)BB * DD + (size_t)b * TT;  // weights region
    float* cout = out + (size_t)b * DD;                    // context region

    const int tid = threadIdx.x;
    __shared__ float red[8];
    __shared__ float s_max, s_sum;

    // ---- masked max ----
    float m = -1e30f;
    for (int t = tid; t < len; t += 256) m = fmaxf(m, e[t]);
    #pragma unroll
    for (int o = 16; o; o >>= 1) m = fmaxf(m, __shfl_xor_sync(0xffffffffu, m, o));
    if ((tid & 31) == 0) red[tid >> 5] = m;
    __syncthreads();
    if (tid == 0) {
        float mm = red[0];
        #pragma unroll
        for (int j = 1; j < 8; j++) mm = fmaxf(mm, red[j]);
        s_max = mm;
    }
    __syncthreads();
    const float bm = s_max;

    // ---- exp-sum ----
    float s = 0.f;
    for (int t = tid; t < len; t += 256) s += __expf(e[t] - bm);
    #pragma unroll
    for (int o = 16; o; o >>= 1) s += __shfl_xor_sync(0xffffffffu, s, o);
    __syncthreads();
    if ((tid & 31) == 0) red[tid >> 5] = s;
    __syncthreads();
    if (tid == 0) {
        float ss = red[0];
        #pragma unroll
        for (int j = 1; j < 8; j++) ss += red[j];
        s_sum = ss;
    }
    __syncthreads();
    const float inv = 1.0f / s_sum;

    // ---- write weights (0 for masked t) ----
    for (int t = tid; t < TT; t += 256)
        wout[t] = (t < len) ? __expf(e[t] - bm) * inv : 0.0f;

    // ---- zero context region for kernel 3's atomics ----
    for (int i = tid; i < DD; i += 256) cout[i] = 0.0f;
}

// ---------------------------------------------------------------------------
// Kernel 3: context[b,:] = sum_t weights[b,t] * value[b,t,:]
// ---------------------------------------------------------------------------
__global__ void __launch_bounds__(256) context_kernel(
    const float* __restrict__ value,
    const int* __restrict__ lens,
    float* __restrict__ out)
{
    const int b = blockIdx.y;
    const int len = __ldg(lens + b);
    const int t0 = blockIdx.x * CHUNK;
    if (t0 >= len) return;
    const int tend = min(t0 + CHUNK, len);

    __shared__ float sw[CHUNK];
    const float* wsrc = out + (size_t)BB * DD + (size_t)b * TT;
    if (threadIdx.x < CHUNK) sw[threadIdx.x] = wsrc[t0 + threadIdx.x];
    __syncthreads();

    const int i = threadIdx.x;  // 0..255 -> one float4 of D
    float4 acc = make_float4(0.f, 0.f, 0.f, 0.f);
    const float4* vb = reinterpret_cast<const float4*>(value)
                     + ((size_t)b * TT + t0) * (DD / 4);

    #pragma unroll 8
    for (int t = t0; t < tend; ++t) {
        const float w = sw[t - t0];
        float4 vv = __ldcs(vb + i);
        acc.x += w * vv.x;
        acc.y += w * vv.y;
        acc.z += w * vv.z;
        acc.w += w * vv.w;
        vb += DD / 4;
    }

    float* cout = out + (size_t)b * DD + i * 4;
    atomicAdd(cout + 0, acc.x);
    atomicAdd(cout + 1, acc.y);
    atomicAdd(cout + 2, acc.z);
    atomicAdd(cout + 3, acc.w);
}

// ---------------------------------------------------------------------------
extern "C" void kernel_launch(void* const* d_in, const int* in_sizes, int n_in,
                              void* d_out, int out_size)
{
    const float* keys  = (const float*)d_in[0];
    const float* value = (const float*)d_in[1];
    const float* query = (const float*)d_in[2];
    const float* wf    = (const float*)d_in[3];
    const float* v     = (const float*)d_in[4];
    const int*   lens  = (const int*)d_in[5];
    float* out = (float*)d_out;

    prefix_kernel<<<1, 32>>>(lens);
    energy_kernel<<<EGRID, 256>>>(keys, query, wf, v);
    softmax_kernel<<<BB, 256>>>(lens, out);
    context_kernel<<<dim3(TT / CHUNK, BB), 256>>>(value, lens, out);
}

// round 8
// speedup vs baseline: 1.0831x; 1.0831x over previous
#include <cuda_runtime.h>

#define BB 32
#define TT 2048
#define DD 1024
#define CHUNK 32
#define ROWS_PER_BLK 8   // 8 warps per block, warp-per-row

// Scratch for energies (device global: no allocation allowed in kernel_launch)
__device__ float g_energies[BB * TT];

__device__ __forceinline__ float fast_tanh(float x) {
    float y;
    asm("tanh.approx.f32 %0, %1;" : "=f"(y) : "f"(x));
    return y;
}

// ---------------------------------------------------------------------------
// Kernel 1: energies[b,t] = sum_d v[d] * tanh(keys[b,t,d] + query[b,d] + wf[b,t,d])
// Warp-per-row (R4-proven form): each warp owns one t, 8 strided float4 loads
// of keys and wf, warp-shfl reduce, no smem/barriers. Masked rows exit early.
// ---------------------------------------------------------------------------
__global__ void __launch_bounds__(256) energy_kernel(
    const float* __restrict__ keys,
    const float* __restrict__ query,
    const float* __restrict__ wf,
    const float* __restrict__ v,
    const int* __restrict__ lens)
{
    const int b    = blockIdx.y;
    const int len  = __ldg(lens + b);
    const int warp = threadIdx.x >> 5;
    const int lane = threadIdx.x & 31;
    const int t    = blockIdx.x * ROWS_PER_BLK + warp;
    if (t >= len) return;

    const size_t row = ((size_t)b * TT + t) * DD;
    const float4* k4 = reinterpret_cast<const float4*>(keys + row);
    const float4* f4 = reinterpret_cast<const float4*>(wf + row);
    const float4* q4 = reinterpret_cast<const float4*>(query + (size_t)b * DD);
    const float4* v4 = reinterpret_cast<const float4*>(v);

    float s = 0.0f;
    #pragma unroll
    for (int j = 0; j < DD / 4 / 32; ++j) {      // 8 iterations
        const int idx = lane + 32 * j;
        float4 kk = k4[idx];
        float4 ff = f4[idx];
        float4 qq = __ldg(q4 + idx);
        float4 vv = __ldg(v4 + idx);
        s += vv.x * fast_tanh(kk.x + qq.x + ff.x)
           + vv.y * fast_tanh(kk.y + qq.y + ff.y)
           + vv.z * fast_tanh(kk.z + qq.z + ff.z)
           + vv.w * fast_tanh(kk.w + qq.w + ff.w);
    }

    // warp reduce
    #pragma unroll
    for (int o = 16; o; o >>= 1) s += __shfl_xor_sync(0xffffffffu, s, o);
    if (lane == 0) g_energies[b * TT + t] = s;
}

// ---------------------------------------------------------------------------
// Kernel 2: per-batch masked softmax -> weights region; zero context region.
// One block per b. Energies are L2-resident (256 KB total).
// ---------------------------------------------------------------------------
__global__ void __launch_bounds__(256) softmax_kernel(
    const int* __restrict__ lens,
    float* __restrict__ out)
{
    const int b = blockIdx.x;
    const int len = __ldg(lens + b);
    const float* e = g_energies + b * TT;
    float* wout = out + (size_t)BB * DD + (size_t)b * TT;  // weights region
    float* cout = out + (size_t)b * DD;                    // context region

    const int tid = threadIdx.x;
    __shared__ float red[8];
    __shared__ float s_max, s_sum;

    // ---- masked max ----
    float m = -1e30f;
    for (int t = tid; t < len; t += 256) m = fmaxf(m, e[t]);
    #pragma unroll
    for (int o = 16; o; o >>= 1) m = fmaxf(m, __shfl_xor_sync(0xffffffffu, m, o));
    if ((tid & 31) == 0) red[tid >> 5] = m;
    __syncthreads();
    if (tid == 0) {
        float mm = red[0];
        #pragma unroll
        for (int j = 1; j < 8; j++) mm = fmaxf(mm, red[j]);
        s_max = mm;
    }
    __syncthreads();
    const float bm = s_max;

    // ---- exp-sum ----
    float s = 0.f;
    for (int t = tid; t < len; t += 256) s += __expf(e[t] - bm);
    #pragma unroll
    for (int o = 16; o; o >>= 1) s += __shfl_xor_sync(0xffffffffu, s, o);
    __syncthreads();
    if ((tid & 31) == 0) red[tid >> 5] = s;
    __syncthreads();
    if (tid == 0) {
        float ss = red[0];
        #pragma unroll
        for (int j = 1; j < 8; j++) ss += red[j];
        s_sum = ss;
    }
    __syncthreads();
    const float inv = 1.0f / s_sum;

    // ---- write weights (0 for masked t) ----
    for (int t = tid; t < TT; t += 256)
        wout[t] = (t < len) ? __expf(e[t] - bm) * inv : 0.0f;

    // ---- zero context region for kernel 3's atomics ----
    for (int i = tid; i < DD; i += 256) cout[i] = 0.0f;
}

// ---------------------------------------------------------------------------
// Kernel 3: context[b,:] = sum_t weights[b,t] * value[b,t,:]
// Grid (T/CHUNK, B), CHUNK=32 for fine-grained balance. Each block accumulates
// a 32-long t-slab over full D in registers, then atomicAdd into context.
// Masked slabs exit early; finer chunks cut the wave-tail raggedness.
// ---------------------------------------------------------------------------
__global__ void __launch_bounds__(256) context_kernel(
    const float* __restrict__ value,
    const int* __restrict__ lens,
    float* __restrict__ out)
{
    const int b = blockIdx.y;
    const int len = __ldg(lens + b);
    const int t0 = blockIdx.x * CHUNK;
    if (t0 >= len) return;
    const int tend = min(t0 + CHUNK, len);

    __shared__ float sw[CHUNK];
    const float* wsrc = out + (size_t)BB * DD + (size_t)b * TT;
    if (threadIdx.x < CHUNK) sw[threadIdx.x] = wsrc[t0 + threadIdx.x];
    __syncthreads();

    const int i = threadIdx.x;  // 0..255 -> one float4 of D
    float4 acc = make_float4(0.f, 0.f, 0.f, 0.f);
    const float4* vb = reinterpret_cast<const float4*>(value)
                     + ((size_t)b * TT + t0) * (DD / 4);

    #pragma unroll 8
    for (int t = t0; t < tend; ++t) {
        const float w = sw[t - t0];
        float4 vv = __ldcs(vb + i);
        acc.x += w * vv.x;
        acc.y += w * vv.y;
        acc.z += w * vv.z;
        acc.w += w * vv.w;
        vb += DD / 4;
    }

    float* cout = out + (size_t)b * DD + i * 4;
    atomicAdd(cout + 0, acc.x);
    atomicAdd(cout + 1, acc.y);
    atomicAdd(cout + 2, acc.z);
    atomicAdd(cout + 3, acc.w);
}

// ---------------------------------------------------------------------------
extern "C" void kernel_launch(void* const* d_in, const int* in_sizes, int n_in,
                              void* d_out, int out_size)
{
    const float* keys  = (const float*)d_in[0];
    const float* value = (const float*)d_in[1];
    const float* query = (const float*)d_in[2];
    const float* wf    = (const float*)d_in[3];
    const float* v     = (const float*)d_in[4];
    const int*   lens  = (const int*)d_in[5];
    float* out = (float*)d_out;

    energy_kernel<<<dim3(TT / ROWS_PER_BLK, BB), 256>>>(keys, query, wf, v, lens);
    softmax_kernel<<<BB, 256>>>(lens, out);
    context_kernel<<<dim3(TT / CHUNK, BB), 256>>>(value, lens, out);
}

// round 9
// speedup vs baseline: 1.1157x; 1.0302x over previous
#include <cuda_runtime.h>

#define BB 32
#define TT 2048
#define DD 1024
#define CHUNK 64
#define ROWS_PER_BLK 8   // 8 warps per block, warp-per-row

// Scratch for energies (device global: no allocation allowed in kernel_launch)
__device__ float g_energies[BB * TT];

__device__ __forceinline__ float fast_tanh(float x) {
    float y;
    asm("tanh.approx.f32 %0, %1;" : "=f"(y) : "f"(x));
    return y;
}

// ---------------------------------------------------------------------------
// Kernel 1: energies[b,t] = sum_d v[d] * tanh(keys[b,t,d] + query[b,d] + wf[b,t,d])
// Warp-per-row (R4-proven fastest form): each warp owns one t, 8 strided
// float4 loads of keys and wf, warp-shfl reduce, no smem/barriers.
// Masked rows exit early -> skip ~half the HBM traffic.
// ---------------------------------------------------------------------------
__global__ void __launch_bounds__(256) energy_kernel(
    const float* __restrict__ keys,
    const float* __restrict__ query,
    const float* __restrict__ wf,
    const float* __restrict__ v,
    const int* __restrict__ lens)
{
    const int b    = blockIdx.y;
    const int len  = __ldg(lens + b);
    const int warp = threadIdx.x >> 5;
    const int lane = threadIdx.x & 31;
    const int t    = blockIdx.x * ROWS_PER_BLK + warp;
    if (t >= len) return;

    const size_t row = ((size_t)b * TT + t) * DD;
    const float4* k4 = reinterpret_cast<const float4*>(keys + row);
    const float4* f4 = reinterpret_cast<const float4*>(wf + row);
    const float4* q4 = reinterpret_cast<const float4*>(query + (size_t)b * DD);
    const float4* v4 = reinterpret_cast<const float4*>(v);

    float s = 0.0f;
    #pragma unroll
    for (int j = 0; j < DD / 4 / 32; ++j) {      // 8 iterations
        const int idx = lane + 32 * j;
        float4 kk = k4[idx];
        float4 ff = f4[idx];
        float4 qq = __ldg(q4 + idx);
        float4 vv = __ldg(v4 + idx);
        s += vv.x * fast_tanh(kk.x + qq.x + ff.x)
           + vv.y * fast_tanh(kk.y + qq.y + ff.y)
           + vv.z * fast_tanh(kk.z + qq.z + ff.z)
           + vv.w * fast_tanh(kk.w + qq.w + ff.w);
    }

    // warp reduce
    #pragma unroll
    for (int o = 16; o; o >>= 1) s += __shfl_xor_sync(0xffffffffu, s, o);
    if (lane == 0) g_energies[b * TT + t] = s;
}

// ---------------------------------------------------------------------------
// Kernel 2: per-batch masked softmax -> weights region; zero context region.
// One block per b. Energies are L2-resident (256 KB total).
// ---------------------------------------------------------------------------
__global__ void __launch_bounds__(256) softmax_kernel(
    const int* __restrict__ lens,
    float* __restrict__ out)
{
    const int b = blockIdx.x;
    const int len = __ldg(lens + b);
    const float* e = g_energies + b * TT;
    float* wout = out + (size_t)BB * DD + (size_t)b * TT;  // weights region
    float* cout = out + (size_t)b * DD;                    // context region

    const int tid = threadIdx.x;
    __shared__ float red[8];
    __shared__ float s_max, s_sum;

    // ---- masked max ----
    float m = -1e30f;
    for (int t = tid; t < len; t += 256) m = fmaxf(m, e[t]);
    #pragma unroll
    for (int o = 16; o; o >>= 1) m = fmaxf(m, __shfl_xor_sync(0xffffffffu, m, o));
    if ((tid & 31) == 0) red[tid >> 5] = m;
    __syncthreads();
    if (tid == 0) {
        float mm = red[0];
        #pragma unroll
        for (int j = 1; j < 8; j++) mm = fmaxf(mm, red[j]);
        s_max = mm;
    }
    __syncthreads();
    const float bm = s_max;

    // ---- exp-sum ----
    float s = 0.f;
    for (int t = tid; t < len; t += 256) s += __expf(e[t] - bm);
    #pragma unroll
    for (int o = 16; o; o >>= 1) s += __shfl_xor_sync(0xffffffffu, s, o);
    __syncthreads();
    if ((tid & 31) == 0) red[tid >> 5] = s;
    __syncthreads();
    if (tid == 0) {
        float ss = red[0];
        #pragma unroll
        for (int j = 1; j < 8; j++) ss += red[j];
        s_sum = ss;
    }
    __syncthreads();
    const float inv = 1.0f / s_sum;

    // ---- write weights (0 for masked t) ----
    for (int t = tid; t < TT; t += 256)
        wout[t] = (t < len) ? __expf(e[t] - bm) * inv : 0.0f;

    // ---- zero context region for kernel 3's atomics ----
    for (int i = tid; i < DD; i += 256) cout[i] = 0.0f;
}

// ---------------------------------------------------------------------------
// Kernel 3: context[b,:] = sum_t weights[b,t] * value[b,t,:]
// Grid (T/CHUNK, B), CHUNK=64 (R5-proven best). Each block accumulates a
// 64-long t-slab over full D in registers, then atomicAdd into context.
// __ldcs on value (streaming, no reuse). Masked slabs exit early.
// ---------------------------------------------------------------------------
__global__ void __launch_bounds__(256) context_kernel(
    const float* __restrict__ value,
    const int* __restrict__ lens,
    float* __restrict__ out)
{
    const int b = blockIdx.y;
    const int len = __ldg(lens + b);
    const int t0 = blockIdx.x * CHUNK;
    if (t0 >= len) return;
    const int tend = min(t0 + CHUNK, len);

    __shared__ float sw[CHUNK];
    const float* wsrc = out + (size_t)BB * DD + (size_t)b * TT;
    if (threadIdx.x < CHUNK) sw[threadIdx.x] = wsrc[t0 + threadIdx.x];
    __syncthreads();

    const int i = threadIdx.x;  // 0..255 -> one float4 of D
    float4 acc = make_float4(0.f, 0.f, 0.f, 0.f);
    const float4* vb = reinterpret_cast<const float4*>(value)
                     + ((size_t)b * TT + t0) * (DD / 4);

    #pragma unroll 8
    for (int t = t0; t < tend; ++t) {
        const float w = sw[t - t0];
        float4 vv = __ldcs(vb + i);
        acc.x += w * vv.x;
        acc.y += w * vv.y;
        acc.z += w * vv.z;
        acc.w += w * vv.w;
        vb += DD / 4;
    }

    float* cout = out + (size_t)b * DD + i * 4;
    atomicAdd(cout + 0, acc.x);
    atomicAdd(cout + 1, acc.y);
    atomicAdd(cout + 2, acc.z);
    atomicAdd(cout + 3, acc.w);
}

// ---------------------------------------------------------------------------
extern "C" void kernel_launch(void* const* d_in, const int* in_sizes, int n_in,
                              void* d_out, int out_size)
{
    const float* keys  = (const float*)d_in[0];
    const float* value = (const float*)d_in[1];
    const float* query = (const float*)d_in[2];
    const float* wf    = (const float*)d_in[3];
    const float* v     = (const float*)d_in[4];
    const int*   lens  = (const int*)d_in[5];
    float* out = (float*)d_out;

    energy_kernel<<<dim3(TT / ROWS_PER_BLK, BB), 256>>>(keys, query, wf, v, lens);
    softmax_kernel<<<BB, 256>>>(lens, out);
    context_kernel<<<dim3(TT / CHUNK, BB), 256>>>(value, lens, out);
}